// round 1
// baseline (speedup 1.0000x reference)
#include <cuda_runtime.h>
#include <cstddef>

// Problem constants
#define B_  4
#define LQ  512
#define LK  2048
#define E_  1024
#define H_  16
#define DH  64
#define F_  4096
#define MQ  (B_*LQ)    // 2048
#define MK  (B_*LK)    // 8192

// ---------------- scratch (device globals; no allocation allowed) ----------
__device__ float g_q[MQ * E_];        // 8 MB   Q projection
__device__ float g_k[MK * E_];        // 32 MB  K projection
__device__ float g_v[MK * E_];        // 32 MB  V projection
__device__ float g_ctx[MQ * E_];      // 8 MB   attention context
__device__ float g_attnout[MQ * E_];  // 8 MB   O projection
__device__ float g_q2[MQ * E_];       // 8 MB   post-LN1
__device__ float g_ffn1[MQ * F_];     // 32 MB  FFN hidden
__device__ float g_ffn2[MQ * E_];     // 8 MB   FFN out

// ---------------------------------------------------------------------------
// Generic NT GEMM: C[m,n] = sum_k A[m,k]*W[n,k] + bias[n]   (optional ReLU)
// A: [M,K] row-major, W: [N,K] row-major (torch Linear weight), C: [M,N].
// 128x128 tile, BK=16, 256 threads, 8x8 micro-tile.
// Requires M%128==0, N%128==0, K%16==0 (true for all calls here).
// ---------------------------------------------------------------------------
__global__ __launch_bounds__(256)
void gemm_nt_bias(const float* __restrict__ A, const float* __restrict__ W,
                  const float* __restrict__ bias, float* __restrict__ C,
                  int M, int N, int K, int relu)
{
    __shared__ float As[16][128];
    __shared__ float Bs[16][128];

    const int tid = threadIdx.x;
    const int tx  = tid & 15;
    const int ty  = tid >> 4;
    const int bm  = blockIdx.y * 128;
    const int bn  = blockIdx.x * 128;

    float acc[8][8];
    #pragma unroll
    for (int i = 0; i < 8; i++)
        #pragma unroll
        for (int j = 0; j < 8; j++) acc[i][j] = 0.f;

    for (int k0 = 0; k0 < K; k0 += 16) {
        #pragma unroll
        for (int l = 0; l < 2; l++) {
            int idx = tid + l * 256;          // 0..511
            int row = idx >> 2;               // 0..127
            int kq  = (idx & 3) << 2;         // 0,4,8,12
            float4 a = *(const float4*)&A[(size_t)(bm + row) * K + k0 + kq];
            As[kq+0][row] = a.x; As[kq+1][row] = a.y;
            As[kq+2][row] = a.z; As[kq+3][row] = a.w;
            float4 b = *(const float4*)&W[(size_t)(bn + row) * K + k0 + kq];
            Bs[kq+0][row] = b.x; Bs[kq+1][row] = b.y;
            Bs[kq+2][row] = b.z; Bs[kq+3][row] = b.w;
        }
        __syncthreads();

        #pragma unroll
        for (int k = 0; k < 16; k++) {
            float a[8], b[8];
            const float4* ap = (const float4*)&As[k][ty * 8];
            const float4* bp = (const float4*)&Bs[k][tx * 8];
            float4 a0 = ap[0], a1 = ap[1];
            float4 b0 = bp[0], b1 = bp[1];
            a[0]=a0.x; a[1]=a0.y; a[2]=a0.z; a[3]=a0.w;
            a[4]=a1.x; a[5]=a1.y; a[6]=a1.z; a[7]=a1.w;
            b[0]=b0.x; b[1]=b0.y; b[2]=b0.z; b[3]=b0.w;
            b[4]=b1.x; b[5]=b1.y; b[6]=b1.z; b[7]=b1.w;
            #pragma unroll
            for (int i = 0; i < 8; i++)
                #pragma unroll
                for (int j = 0; j < 8; j++)
                    acc[i][j] = fmaf(a[i], b[j], acc[i][j]);
        }
        __syncthreads();
    }

    #pragma unroll
    for (int i = 0; i < 8; i++) {
        int m = bm + ty * 8 + i;
        #pragma unroll
        for (int j = 0; j < 8; j += 4) {
            int n = bn + tx * 8 + j;
            float4 o;
            o.x = acc[i][j+0] + bias[n+0];
            o.y = acc[i][j+1] + bias[n+1];
            o.z = acc[i][j+2] + bias[n+2];
            o.w = acc[i][j+3] + bias[n+3];
            if (relu) {
                o.x = fmaxf(o.x, 0.f); o.y = fmaxf(o.y, 0.f);
                o.z = fmaxf(o.z, 0.f); o.w = fmaxf(o.w, 0.f);
            }
            *(float4*)&C[(size_t)m * N + n] = o;
        }
    }
}

// ---------------------------------------------------------------------------
// scores[b,h,q,k] = (q_h . k_h) / 8   per head GEMM M=512,N=2048,K=64
// 64x64 tile, 256 threads, 4x4 micro-tile. grid (LK/64, LQ/64, B*H)
// ---------------------------------------------------------------------------
__global__ __launch_bounds__(256)
void scores_kernel(const float* __restrict__ q, const float* __restrict__ k,
                   float* __restrict__ attn)
{
    __shared__ float As[16][64];
    __shared__ float Bs[16][64];

    const int bh = blockIdx.z;
    const int b  = bh >> 4;
    const int h  = bh & 15;
    const int bm = blockIdx.y * 64;
    const int bn = blockIdx.x * 64;

    const int tid = threadIdx.x;
    const int tx  = tid & 15;
    const int ty  = tid >> 4;

    const float* qb = q + (size_t)b * LQ * E_ + h * DH;
    const float* kb = k + (size_t)b * LK * E_ + h * DH;

    float acc[4][4];
    #pragma unroll
    for (int i = 0; i < 4; i++)
        #pragma unroll
        for (int j = 0; j < 4; j++) acc[i][j] = 0.f;

    #pragma unroll
    for (int k0 = 0; k0 < DH; k0 += 16) {
        int row = tid >> 2;          // 0..63
        int kq  = (tid & 3) << 2;    // 0,4,8,12
        float4 a = *(const float4*)&qb[(size_t)(bm + row) * E_ + k0 + kq];
        As[kq+0][row] = a.x; As[kq+1][row] = a.y;
        As[kq+2][row] = a.z; As[kq+3][row] = a.w;
        float4 bb = *(const float4*)&kb[(size_t)(bn + row) * E_ + k0 + kq];
        Bs[kq+0][row] = bb.x; Bs[kq+1][row] = bb.y;
        Bs[kq+2][row] = bb.z; Bs[kq+3][row] = bb.w;
        __syncthreads();

        #pragma unroll
        for (int kk = 0; kk < 16; kk++) {
            float4 a4 = *(const float4*)&As[kk][ty * 4];
            float4 b4 = *(const float4*)&Bs[kk][tx * 4];
            float a[4] = {a4.x, a4.y, a4.z, a4.w};
            float bb2[4] = {b4.x, b4.y, b4.z, b4.w};
            #pragma unroll
            for (int i = 0; i < 4; i++)
                #pragma unroll
                for (int j = 0; j < 4; j++)
                    acc[i][j] = fmaf(a[i], bb2[j], acc[i][j]);
        }
        __syncthreads();
    }

    float* out = attn + ((size_t)bh * LQ + bm) * LK + bn;
    #pragma unroll
    for (int i = 0; i < 4; i++) {
        float4 o;
        o.x = acc[i][0] * 0.125f;
        o.y = acc[i][1] * 0.125f;
        o.z = acc[i][2] * 0.125f;
        o.w = acc[i][3] * 0.125f;
        *(float4*)&out[(size_t)(ty * 4 + i) * LK + tx * 4] = o;
    }
}

// ---------------------------------------------------------------------------
// In-place softmax over rows of length 2048. One block (256 thr) per row.
// ---------------------------------------------------------------------------
__global__ __launch_bounds__(256)
void softmax2048(float* __restrict__ attn)
{
    float* p = attn + (size_t)blockIdx.x * LK;
    const int t = threadIdx.x;

    float4 v0 = ((float4*)p)[t];
    float4 v1 = ((float4*)p)[t + 256];

    float m = fmaxf(fmaxf(fmaxf(v0.x, v0.y), fmaxf(v0.z, v0.w)),
                    fmaxf(fmaxf(v1.x, v1.y), fmaxf(v1.z, v1.w)));

    __shared__ float rmax[8];
    __shared__ float rsum[8];
    #pragma unroll
    for (int o = 16; o > 0; o >>= 1)
        m = fmaxf(m, __shfl_xor_sync(0xffffffffu, m, o));
    if ((t & 31) == 0) rmax[t >> 5] = m;
    __syncthreads();
    m = rmax[0];
    #pragma unroll
    for (int i = 1; i < 8; i++) m = fmaxf(m, rmax[i]);

    v0.x = __expf(v0.x - m); v0.y = __expf(v0.y - m);
    v0.z = __expf(v0.z - m); v0.w = __expf(v0.w - m);
    v1.x = __expf(v1.x - m); v1.y = __expf(v1.y - m);
    v1.z = __expf(v1.z - m); v1.w = __expf(v1.w - m);

    float s = v0.x + v0.y + v0.z + v0.w + v1.x + v1.y + v1.z + v1.w;
    #pragma unroll
    for (int o = 16; o > 0; o >>= 1)
        s += __shfl_xor_sync(0xffffffffu, s, o);
    if ((t & 31) == 0) rsum[t >> 5] = s;
    __syncthreads();
    s = rsum[0];
    #pragma unroll
    for (int i = 1; i < 8; i++) s += rsum[i];

    float r = 1.0f / s;
    v0.x *= r; v0.y *= r; v0.z *= r; v0.w *= r;
    v1.x *= r; v1.y *= r; v1.z *= r; v1.w *= r;

    ((float4*)p)[t]       = v0;
    ((float4*)p)[t + 256] = v1;
}

// ---------------------------------------------------------------------------
// ctx[b,q,h*64+d] = sum_k attn[b,h,q,k] * v[b,k,h*64+d]
// per head GEMM M=512, N=64, K=2048.  64(m)x64(n) tile. grid (LQ/64, B*H)
// ---------------------------------------------------------------------------
__global__ __launch_bounds__(256)
void ctx_kernel(const float* __restrict__ attn, const float* __restrict__ v,
                float* __restrict__ ctx)
{
    __shared__ float As[16][64];   // As[k][m]
    __shared__ float Bs[16][64];   // Bs[k][n]

    const int bh = blockIdx.y;
    const int b  = bh >> 4;
    const int h  = bh & 15;
    const int bm = blockIdx.x * 64;

    const int tid = threadIdx.x;
    const int tx  = tid & 15;
    const int ty  = tid >> 4;

    const float* Ab = attn + ((size_t)bh * LQ + bm) * LK;
    const float* Vb = v + (size_t)b * LK * E_ + h * DH;

    float acc[4][4];
    #pragma unroll
    for (int i = 0; i < 4; i++)
        #pragma unroll
        for (int j = 0; j < 4; j++) acc[i][j] = 0.f;

    for (int k0 = 0; k0 < LK; k0 += 16) {
        // A tile 64m x 16k
        int row = tid >> 2;
        int kq  = (tid & 3) << 2;
        float4 a = *(const float4*)&Ab[(size_t)row * LK + k0 + kq];
        As[kq+0][row] = a.x; As[kq+1][row] = a.y;
        As[kq+2][row] = a.z; As[kq+3][row] = a.w;
        // B tile 16k x 64n (n contiguous)
        int kr = tid >> 4;            // 0..15
        int nq = (tid & 15) << 2;     // 0..60
        float4 bb = *(const float4*)&Vb[(size_t)(k0 + kr) * E_ + nq];
        *(float4*)&Bs[kr][nq] = bb;
        __syncthreads();

        #pragma unroll
        for (int kk = 0; kk < 16; kk++) {
            float4 a4 = *(const float4*)&As[kk][ty * 4];
            float4 b4 = *(const float4*)&Bs[kk][tx * 4];
            float a2[4] = {a4.x, a4.y, a4.z, a4.w};
            float b2[4] = {b4.x, b4.y, b4.z, b4.w};
            #pragma unroll
            for (int i = 0; i < 4; i++)
                #pragma unroll
                for (int j = 0; j < 4; j++)
                    acc[i][j] = fmaf(a2[i], b2[j], acc[i][j]);
        }
        __syncthreads();
    }

    #pragma unroll
    for (int i = 0; i < 4; i++) {
        size_t m = (size_t)b * LQ + bm + ty * 4 + i;
        float4 o = make_float4(acc[i][0], acc[i][1], acc[i][2], acc[i][3]);
        *(float4*)&ctx[m * E_ + h * DH + tx * 4] = o;
    }
}

// ---------------------------------------------------------------------------
// out = LayerNorm(a + b) * g + beta   over rows of 1024. 1 block/row, 256 thr.
// ---------------------------------------------------------------------------
__global__ __launch_bounds__(256)
void ln_residual(const float* __restrict__ A, const float* __restrict__ Bx,
                 const float* __restrict__ g, const float* __restrict__ be,
                 float* __restrict__ out)
{
    const size_t row = blockIdx.x;
    const int t = threadIdx.x;

    float4 a = ((const float4*)(A  + row * E_))[t];
    float4 b = ((const float4*)(Bx + row * E_))[t];
    float4 x = make_float4(a.x + b.x, a.y + b.y, a.z + b.z, a.w + b.w);

    float s  = x.x + x.y + x.z + x.w;
    float ss = x.x*x.x + x.y*x.y + x.z*x.z + x.w*x.w;

    __shared__ float rs[8], rss[8];
    #pragma unroll
    for (int o = 16; o > 0; o >>= 1) {
        s  += __shfl_xor_sync(0xffffffffu, s,  o);
        ss += __shfl_xor_sync(0xffffffffu, ss, o);
    }
    if ((t & 31) == 0) { rs[t >> 5] = s; rss[t >> 5] = ss; }
    __syncthreads();
    s = 0.f; ss = 0.f;
    #pragma unroll
    for (int i = 0; i < 8; i++) { s += rs[i]; ss += rss[i]; }

    const float mean = s * (1.0f / E_);
    const float var  = ss * (1.0f / E_) - mean * mean;
    const float inv  = rsqrtf(var + 1e-5f);

    float4 gg = ((const float4*)g)[t];
    float4 bb = ((const float4*)be)[t];
    float4 o;
    o.x = (x.x - mean) * inv * gg.x + bb.x;
    o.y = (x.y - mean) * inv * gg.y + bb.y;
    o.z = (x.z - mean) * inv * gg.z + bb.z;
    o.w = (x.w - mean) * inv * gg.w + bb.w;
    ((float4*)(out + row * E_))[t] = o;
}

// ---------------------------------------------------------------------------
extern "C" void kernel_launch(void* const* d_in, const int* in_sizes, int n_in,
                              void* d_out, int out_size)
{
    const float* query = (const float*)d_in[0];
    const float* keyv  = (const float*)d_in[1];
    const float* wq = (const float*)d_in[2];
    const float* wk = (const float*)d_in[3];
    const float* wv = (const float*)d_in[4];
    const float* bq = (const float*)d_in[5];
    const float* bk = (const float*)d_in[6];
    const float* bv = (const float*)d_in[7];
    const float* wo = (const float*)d_in[8];
    const float* bo = (const float*)d_in[9];
    const float* g1 = (const float*)d_in[10];
    const float* be1 = (const float*)d_in[11];
    const float* w1 = (const float*)d_in[12];
    const float* b1 = (const float*)d_in[13];
    const float* w2 = (const float*)d_in[14];
    const float* b2 = (const float*)d_in[15];
    const float* g2 = (const float*)d_in[16];
    const float* be2 = (const float*)d_in[17];

    float* out = (float*)d_out;
    float* q3_out = out;                       // [B,LQ,E]
    float* attn   = out + (size_t)MQ * E_;     // [B,H,LQ,LK]

    float *gq, *gk, *gv, *gctx, *gao, *gq2, *gf1, *gf2;
    cudaGetSymbolAddress((void**)&gq,  g_q);
    cudaGetSymbolAddress((void**)&gk,  g_k);
    cudaGetSymbolAddress((void**)&gv,  g_v);
    cudaGetSymbolAddress((void**)&gctx, g_ctx);
    cudaGetSymbolAddress((void**)&gao, g_attnout);
    cudaGetSymbolAddress((void**)&gq2, g_q2);
    cudaGetSymbolAddress((void**)&gf1, g_ffn1);
    cudaGetSymbolAddress((void**)&gf2, g_ffn2);

    // Q/K/V projections
    gemm_nt_bias<<<dim3(E_/128, MQ/128), 256>>>(query, wq, bq, gq, MQ, E_, E_, 0);
    gemm_nt_bias<<<dim3(E_/128, MK/128), 256>>>(keyv,  wk, bk, gk, MK, E_, E_, 0);
    gemm_nt_bias<<<dim3(E_/128, MK/128), 256>>>(keyv,  wv, bv, gv, MK, E_, E_, 0);

    // attention
    scores_kernel<<<dim3(LK/64, LQ/64, B_*H_), 256>>>(gq, gk, attn);
    softmax2048<<<B_*H_*LQ, 256>>>(attn);
    ctx_kernel<<<dim3(LQ/64, B_*H_), 256>>>(attn, gv, gctx);

    // output projection + LN1
    gemm_nt_bias<<<dim3(E_/128, MQ/128), 256>>>(gctx, wo, bo, gao, MQ, E_, E_, 0);
    ln_residual<<<MQ, 256>>>(query, gao, g1, be1, gq2);

    // FFN + LN2
    gemm_nt_bias<<<dim3(F_/128, MQ/128), 256>>>(gq2, w1, b1, gf1, MQ, F_, E_, 1);
    gemm_nt_bias<<<dim3(E_/128, MQ/128), 256>>>(gf1, w2, b2, gf2, MQ, E_, F_, 0);
    ln_residual<<<MQ, 256>>>(gq2, gf2, g2, be2, q3_out);
}